// round 15
// baseline (speedup 1.0000x reference)
#include <cuda_runtime.h>
#include <math.h>

// ---------------- problem constants ----------------
#define S_LEN 4096
#define HIDDEN 4096
#define NH 32
#define NKV 8
#define HD 128
#define QDIM (NH * HD)    // 4096
#define KVDIM (NKV * HD)  // 1024
#define NB (S_LEN / 128)  // 32 query blocks
#define PAD 132           // smem row stride in floats

// ---------------- scratch (device globals; no allocs allowed) ----------------
__device__ float g_q[(size_t)S_LEN * QDIM];    // 64 MB
__device__ float g_k[(size_t)S_LEN * KVDIM];   // 16 MB
__device__ float g_v[(size_t)S_LEN * KVDIM];   // 16 MB
__device__ float g_att[(size_t)S_LEN * QDIM];  // 64 MB

// =====================================================================
// Tiled 128x128x8 SGEMM, C = A(MxK) @ B(KxN), row-major.
// Cross-validated vs naive oracle (bit-identical pipeline output R1/R5).
// =====================================================================
__global__ __launch_bounds__(256) void sgemm_kernel(
    int M, int N, int K,
    const float* __restrict__ A, const float* __restrict__ B,
    float* __restrict__ C) {
  const int BM = 128, BN = 128, BK = 8, TM = 8, TN = 8;
  __shared__ float As[BK * BM];
  __shared__ float Bs[BK * BN];

  const int tid = threadIdx.x;
  const int cRow = blockIdx.y, cCol = blockIdx.x;
  const int threadCol = tid % (BN / TN);
  const int threadRow = tid / (BN / TN);

  A += (size_t)cRow * BM * K;
  B += (size_t)cCol * BN;
  C += (size_t)cRow * BM * N + cCol * BN;

  const int innerRowA = tid / 2;
  const int innerColA = (tid % 2) * 4;
  const int innerRowB = tid / 32;
  const int innerColB = (tid % 32) * 4;

  float acc[TM][TN] = {};
  float regM[TM], regN[TN];

  for (int k0 = 0; k0 < K; k0 += BK) {
    float4 a4 = *reinterpret_cast<const float4*>(&A[(size_t)innerRowA * K + innerColA]);
    As[(innerColA + 0) * BM + innerRowA] = a4.x;
    As[(innerColA + 1) * BM + innerRowA] = a4.y;
    As[(innerColA + 2) * BM + innerRowA] = a4.z;
    As[(innerColA + 3) * BM + innerRowA] = a4.w;
    *reinterpret_cast<float4*>(&Bs[innerRowB * BN + innerColB]) =
        *reinterpret_cast<const float4*>(&B[(size_t)innerRowB * N + innerColB]);
    __syncthreads();
    A += BK;
    B += (size_t)BK * N;
#pragma unroll
    for (int k = 0; k < BK; ++k) {
#pragma unroll
      for (int i = 0; i < TM; i += 4)
        *reinterpret_cast<float4*>(&regM[i]) =
            *reinterpret_cast<float4*>(&As[k * BM + threadRow * TM + i]);
#pragma unroll
      for (int j = 0; j < TN; j += 4)
        *reinterpret_cast<float4*>(&regN[j]) =
            *reinterpret_cast<float4*>(&Bs[k * BN + threadCol * TN + j]);
#pragma unroll
      for (int i = 0; i < TM; ++i)
#pragma unroll
        for (int j = 0; j < TN; ++j) acc[i][j] += regM[i] * regN[j];
    }
    __syncthreads();
  }

#pragma unroll
  for (int i = 0; i < TM; ++i)
#pragma unroll
    for (int j = 0; j < TN; j += 4) {
      float4 o;
      o.x = acc[i][j + 0]; o.y = acc[i][j + 1];
      o.z = acc[i][j + 2]; o.w = acc[i][j + 3];
      *reinterpret_cast<float4*>(
          &C[(size_t)(threadRow * TM + i) * N + threadCol * TN + j]) = o;
    }
}

// =====================================================================
// RoPE — SIGN-FLIPPED HALVES convention (identified by the Round-13
// convention lab: candidate c=2 matched measured eH/eI to 0.1%).
// Pairs (j, j+64), angle = s * 10000^(-j/64), rotation by NEGATIVE angle:
//   out[j]    = x1*cos + x2*sin
//   out[j+64] = x2*cos - x1*sin
// One thread per (s, head, j). heads 0..31 -> g_q, 32..39 -> g_k.
// =====================================================================
__global__ void rope_kernel() {
  int idx = blockIdx.x * blockDim.x + threadIdx.x;
  const int total = S_LEN * (NH + NKV) * 64;
  if (idx >= total) return;
  int j = idx & 63;
  int rest = idx >> 6;
  int head = rest % (NH + NKV);
  int s = rest / (NH + NKV);

  float inv_freq = (float)pow(10000.0, -(double)j / 64.0);
  float ang = (float)s * inv_freq;
  float c, sn;
  sincosf(ang, &c, &sn);

  float* base;
  if (head < NH)
    base = g_q + (size_t)s * QDIM + head * HD;
  else
    base = g_k + (size_t)s * KVDIM + (head - NH) * HD;
  float x1 = base[j], x2 = base[j + 64];
  base[j] = x1 * c + x2 * sn;       // sign-flipped
  base[j + 64] = x2 * c - x1 * sn;  // sign-flipped
}

// =====================================================================
// Block-sparse attention (validated R2 clean-room version).
// =====================================================================
#define ATTN_SMEM_FLOATS (3 * 128 * PAD + 128)
#define ATTN_SMEM_BYTES (ATTN_SMEM_FLOATS * 4)

__global__ __launch_bounds__(256, 1) void attn_kernel() {
  extern __shared__ float sm[];
  float* Qt = sm;
  float* KVt = sm + 128 * PAD;
  float* St = sm + 2 * 128 * PAD;
  float* s_l = sm + 3 * 128 * PAD;

  const int i = blockIdx.x;
  const int h = blockIdx.y;
  const int kvh = h >> 2;
  const int tid = threadIdx.x;
  const int tr = tid >> 4;
  const int tc = tid & 15;
  const float scale = 0.08838834764831845f;  // 1/sqrt(128)

  const float* qg = g_q + (size_t)(i * 128) * QDIM + h * HD;
#pragma unroll
  for (int it = 0; it < 16; ++it) {
    int fid = it * 256 + tid;
    int r = fid >> 5;
    int d0 = (fid & 31) * 4;
    float4 t = *reinterpret_cast<const float4*>(&qg[(size_t)r * QDIM + d0]);
    Qt[(d0 + 0) * PAD + r] = t.x * scale;
    Qt[(d0 + 1) * PAD + r] = t.y * scale;
    Qt[(d0 + 2) * PAD + r] = t.z * scale;
    Qt[(d0 + 3) * PAD + r] = t.w * scale;
  }
  if (tid < 128) s_l[tid] = 0.0f;
  float accO[8][8] = {};
  __syncthreads();

  for (int b = -1; b < 8; ++b) {
    const int kb = (b < 0) ? 0 : (i - 7 + b);
    if (b >= 0 && kb < 1) continue;

    const float* kg = g_k + (size_t)(kb * 128) * KVDIM + kvh * HD;
#pragma unroll
    for (int it = 0; it < 16; ++it) {
      int fid = it * 256 + tid;
      int r = fid >> 5;
      int d0 = (fid & 31) * 4;
      float4 t = *reinterpret_cast<const float4*>(&kg[(size_t)r * KVDIM + d0]);
      KVt[(d0 + 0) * PAD + r] = t.x;
      KVt[(d0 + 1) * PAD + r] = t.y;
      KVt[(d0 + 2) * PAD + r] = t.z;
      KVt[(d0 + 3) * PAD + r] = t.w;
    }
    __syncthreads();

    float accS[8][8] = {};
#pragma unroll 2
    for (int d = 0; d < 128; ++d) {
      float regK[8], regQ[8];
      *reinterpret_cast<float4*>(&regK[0]) =
          *reinterpret_cast<const float4*>(&KVt[d * PAD + tr * 8]);
      *reinterpret_cast<float4*>(&regK[4]) =
          *reinterpret_cast<const float4*>(&KVt[d * PAD + tr * 8 + 4]);
      *reinterpret_cast<float4*>(&regQ[0]) =
          *reinterpret_cast<const float4*>(&Qt[d * PAD + tc * 8]);
      *reinterpret_cast<float4*>(&regQ[4]) =
          *reinterpret_cast<const float4*>(&Qt[d * PAD + tc * 8 + 4]);
#pragma unroll
      for (int a = 0; a < 8; ++a)
#pragma unroll
        for (int c = 0; c < 8; ++c) accS[a][c] += regK[a] * regQ[c];
    }

#pragma unroll
    for (int a = 0; a < 8; ++a) {
      const int kpos = kb * 128 + tr * 8 + a;
      float p[8];
#pragma unroll
      for (int c = 0; c < 8; ++c) {
        const int qpos = i * 128 + tc * 8 + c;
        p[c] = (kpos > qpos) ? 0.0f : expf(accS[a][c]);
      }
      float4 o0, o1;
      o0.x = p[0]; o0.y = p[1]; o0.z = p[2]; o0.w = p[3];
      o1.x = p[4]; o1.y = p[5]; o1.z = p[6]; o1.w = p[7];
      *reinterpret_cast<float4*>(&St[(tr * 8 + a) * PAD + tc * 8]) = o0;
      *reinterpret_cast<float4*>(&St[(tr * 8 + a) * PAD + tc * 8 + 4]) = o1;
    }
    __syncthreads();

    const float* vg = g_v + (size_t)(kb * 128) * KVDIM + kvh * HD;
#pragma unroll
    for (int it = 0; it < 16; ++it) {
      int fid = it * 256 + tid;
      int r = fid >> 5;
      int d0 = (fid & 31) * 4;
      *reinterpret_cast<float4*>(&KVt[r * PAD + d0]) =
          *reinterpret_cast<const float4*>(&vg[(size_t)r * KVDIM + d0]);
    }

    if (tid < 128) {
      const int q = tid;
      float sum = 0.0f;
      for (int k = 0; k < 128; ++k) sum += St[k * PAD + q];
      s_l[q] += sum;
    }
    __syncthreads();

#pragma unroll 2
    for (int k = 0; k < 128; ++k) {
      float regP[8], regV[8];
      *reinterpret_cast<float4*>(&regP[0]) =
          *reinterpret_cast<const float4*>(&St[k * PAD + tr * 8]);
      *reinterpret_cast<float4*>(&regP[4]) =
          *reinterpret_cast<const float4*>(&St[k * PAD + tr * 8 + 4]);
      *reinterpret_cast<float4*>(&regV[0]) =
          *reinterpret_cast<const float4*>(&KVt[k * PAD + tc * 8]);
      *reinterpret_cast<float4*>(&regV[4]) =
          *reinterpret_cast<const float4*>(&KVt[k * PAD + tc * 8 + 4]);
#pragma unroll
      for (int a = 0; a < 8; ++a)
#pragma unroll
        for (int c = 0; c < 8; ++c) accO[a][c] += regP[a] * regV[c];
    }
    __syncthreads();
  }

  float* og = g_att + (size_t)(i * 128) * QDIM + h * HD;
#pragma unroll
  for (int a = 0; a < 8; ++a) {
    float inv = 1.0f / s_l[tr * 8 + a];
    float4 o0, o1;
    o0.x = accO[a][0] * inv; o0.y = accO[a][1] * inv;
    o0.z = accO[a][2] * inv; o0.w = accO[a][3] * inv;
    o1.x = accO[a][4] * inv; o1.y = accO[a][5] * inv;
    o1.z = accO[a][6] * inv; o1.w = accO[a][7] * inv;
    *reinterpret_cast<float4*>(&og[(size_t)(tr * 8 + a) * QDIM + tc * 8]) = o0;
    *reinterpret_cast<float4*>(&og[(size_t)(tr * 8 + a) * QDIM + tc * 8 + 4]) = o1;
  }
}

// =====================================================================
// Launch orchestration (verified wiring: [hs, wq, wk, wv, wo], fp32).
// =====================================================================
extern "C" void kernel_launch(void* const* d_in, const int* in_sizes, int n_in,
                              void* d_out, int out_size) {
  (void)in_sizes; (void)n_in; (void)out_size;
  const float* hs = (const float*)d_in[0];
  const float* wq = (const float*)d_in[1];
  const float* wk = (const float*)d_in[2];
  const float* wv = (const float*)d_in[3];
  const float* wo = (const float*)d_in[4];
  float* out = (float*)d_out;

  float *qp, *kp, *vp, *ap;
  cudaGetSymbolAddress((void**)&qp, g_q);
  cudaGetSymbolAddress((void**)&kp, g_k);
  cudaGetSymbolAddress((void**)&vp, g_v);
  cudaGetSymbolAddress((void**)&ap, g_att);

  cudaFuncSetAttribute(attn_kernel, cudaFuncAttributeMaxDynamicSharedMemorySize,
                       ATTN_SMEM_BYTES);

  sgemm_kernel<<<dim3(QDIM / 128, NB), 256>>>(S_LEN, QDIM, HIDDEN, hs, wq, qp);
  sgemm_kernel<<<dim3(KVDIM / 128, NB), 256>>>(S_LEN, KVDIM, HIDDEN, hs, wk, kp);
  sgemm_kernel<<<dim3(KVDIM / 128, NB), 256>>>(S_LEN, KVDIM, HIDDEN, hs, wv, vp);

  {
    int total = S_LEN * (NH + NKV) * 64;
    rope_kernel<<<(total + 255) / 256, 256>>>();
  }

  attn_kernel<<<dim3(NB, NH), 256, ATTN_SMEM_BYTES>>>();

  sgemm_kernel<<<dim3(QDIM / 128, NB), 256>>>(S_LEN, HIDDEN, QDIM, ap, wo, out);
}

// round 17
// speedup vs baseline: 2.2073x; 2.2073x over previous
#include <cuda_runtime.h>
#include <cuda_bf16.h>
#include <math.h>
#include <stdint.h>

// ---------------- problem constants ----------------
#define S_LEN 4096
#define HIDDEN 4096
#define NH 32
#define NKV 8
#define HD 128
#define QDIM (NH * HD)    // 4096
#define KVDIM (NKV * HD)  // 1024
#define NB (S_LEN / 128)  // 32
#define PAD 132

// ---------------- scratch (device globals; no allocs allowed) ----------------
__device__ float g_q[(size_t)S_LEN * QDIM];
__device__ float g_k[(size_t)S_LEN * KVDIM];
__device__ float g_v[(size_t)S_LEN * KVDIM];
__device__ float g_att[(size_t)S_LEN * QDIM];
__device__ __nv_bfloat16 g_ah[(size_t)S_LEN * HIDDEN];  // A hi [M,K]
__device__ __nv_bfloat16 g_al[(size_t)S_LEN * HIDDEN];  // A lo
__device__ __nv_bfloat16 g_bh[(size_t)HIDDEN * QDIM];   // B hi [N,K]
__device__ __nv_bfloat16 g_bl[(size_t)HIDDEN * QDIM];   // B lo

// ---------------- helpers ----------------
__device__ __forceinline__ uint32_t smem_to_u32(const void* p) {
  uint32_t a;
  asm("{ .reg .u64 t; cvta.to.shared.u64 t, %1; cvt.u32.u64 %0, t; }" : "=r"(a) : "l"(p));
  return a;
}
#define SWZ(off) ((off) ^ (((off) >> 3) & 0x70))

__device__ __forceinline__ void ldsm_x4(uint32_t* r, uint32_t addr) {
  asm volatile("ldmatrix.sync.aligned.m8n8.x4.shared.b16 {%0,%1,%2,%3}, [%4];"
               : "=r"(r[0]), "=r"(r[1]), "=r"(r[2]), "=r"(r[3]) : "r"(addr));
}
__device__ __forceinline__ void mma_bf16(float* d, const uint32_t* a, const uint32_t* b) {
  asm volatile(
      "mma.sync.aligned.m16n8k16.row.col.f32.bf16.bf16.f32 "
      "{%0,%1,%2,%3}, {%4,%5,%6,%7}, {%8,%9}, {%0,%1,%2,%3};"
      : "+f"(d[0]), "+f"(d[1]), "+f"(d[2]), "+f"(d[3])
      : "r"(a[0]), "r"(a[1]), "r"(a[2]), "r"(a[3]), "r"(b[0]), "r"(b[1]));
}
#define CP_ASYNC16(dst, src) \
  asm volatile("cp.async.cg.shared.global [%0], [%1], 16;" :: "r"(dst), "l"(src))
#define CP_COMMIT() asm volatile("cp.async.commit_group;" ::: "memory")
#define CP_WAIT(n) asm volatile("cp.async.wait_group %0;" :: "n"(n) : "memory")

// =====================================================================
// split: fp32 -> (hi, lo) bf16, elementwise
// =====================================================================
__global__ void split_rows(const float* __restrict__ x, __nv_bfloat16* __restrict__ h,
                           __nv_bfloat16* __restrict__ l, long n) {
  long i = (long)blockIdx.x * blockDim.x + threadIdx.x;
  if (i >= n) return;
  float v = x[i];
  __nv_bfloat16 hi = __float2bfloat16(v);
  h[i] = hi;
  l[i] = __float2bfloat16(v - __bfloat162float(hi));
}

// =====================================================================
// transpose + split: w [K,N] fp32 -> bh/bl [N,K] bf16 (32x32 tiles)
// =====================================================================
__global__ void transpose_split(const float* __restrict__ w,
                                __nv_bfloat16* __restrict__ bh,
                                __nv_bfloat16* __restrict__ bl, int K, int N) {
  __shared__ float t[32][33];
  int k0 = blockIdx.y * 32, n0 = blockIdx.x * 32;
  int tx = threadIdx.x, ty = threadIdx.y;  // 32 x 8
#pragma unroll
  for (int i = 0; i < 4; ++i)
    t[ty * 4 + i][tx] = w[(size_t)(k0 + ty * 4 + i) * N + n0 + tx];
  __syncthreads();
#pragma unroll
  for (int i = 0; i < 4; ++i) {
    int n = ty * 4 + i, kk = tx;
    float v = t[kk][n];
    __nv_bfloat16 hi = __float2bfloat16(v);
    bh[(size_t)(n0 + n) * K + k0 + kk] = hi;
    bl[(size_t)(n0 + n) * K + k0 + kk] = __float2bfloat16(v - __bfloat162float(hi));
  }
}

// =====================================================================
// HMMA split-bf16 GEMM: C[M,N] fp32 = (Ah+Al)[M,K] @ (Bh+Bl)^T,
// B given as [N,K]. C = Ah*Bh + Ah*Bl + Al*Bh.
// CTA 128x128, 8 warps (4x2), warp tile 32x64, K-chunk 64, 2-stage cp.async.
// smem per stage: Ah|Al|Bh|Bl, each 128 rows x 128B, SW128-swizzled.
// =====================================================================
#define ST_A_H 0
#define ST_A_L 16384
#define ST_B_H 32768
#define ST_B_L 49152
#define STAGE_BYTES 65536
#define MMA_SMEM (2 * STAGE_BYTES)

__global__ __launch_bounds__(256, 1) void mma_gemm(
    int M, int N, int K,
    const __nv_bfloat16* __restrict__ Ah, const __nv_bfloat16* __restrict__ Al,
    const __nv_bfloat16* __restrict__ Bh, const __nv_bfloat16* __restrict__ Bl,
    float* __restrict__ C) {
  extern __shared__ char smem[];
  const uint32_t sb = smem_to_u32(smem);
  const int tid = threadIdx.x;
  const int wid = tid >> 5, lane = tid & 31;
  const int warp_m = wid & 3, warp_n = wid >> 2;  // 4 x 2 warps
  const int m0 = blockIdx.y * 128, n0 = blockIdx.x * 128;
  const size_t rs = (size_t)K * 2;  // row stride bytes (K-contiguous)
  const int nch = K / 64;

  // per-thread staging coords: 4 (row,c16) pairs covering 128x128B per array
  int srow[4], scol[4];
  uint32_t ssw[4];
#pragma unroll
  for (int p = 0; p < 4; ++p) {
    int fid = p * 256 + tid;
    srow[p] = fid >> 3;
    scol[p] = (fid & 7) * 16;
    ssw[p] = SWZ((uint32_t)(srow[p] * 128 + scol[p]));
  }

  auto prefetch = [&](int ch, int stage) {
    const uint32_t stb = sb + stage * STAGE_BYTES;
    const long kb = (long)ch * 128;  // 64 bf16 = 128 bytes
#pragma unroll
    for (int p = 0; p < 4; ++p) {
      const char* a_h = (const char*)Ah + (size_t)(m0 + srow[p]) * rs + kb + scol[p];
      const char* a_l = (const char*)Al + (size_t)(m0 + srow[p]) * rs + kb + scol[p];
      const char* b_h = (const char*)Bh + (size_t)(n0 + srow[p]) * rs + kb + scol[p];
      const char* b_l = (const char*)Bl + (size_t)(n0 + srow[p]) * rs + kb + scol[p];
      CP_ASYNC16(stb + ST_A_H + ssw[p], a_h);
      CP_ASYNC16(stb + ST_A_L + ssw[p], a_l);
      CP_ASYNC16(stb + ST_B_H + ssw[p], b_h);
      CP_ASYNC16(stb + ST_B_L + ssw[p], b_l);
    }
    CP_COMMIT();
  };

  float acc[2][8][4];
#pragma unroll
  for (int mt = 0; mt < 2; ++mt)
#pragma unroll
    for (int nt = 0; nt < 8; ++nt)
#pragma unroll
      for (int j = 0; j < 4; ++j) acc[mt][nt][j] = 0.0f;

  // ldmatrix lane-fixed parts
  const int lrow_off = (lane & 7) + ((lane >> 3) & 1) * 8;  // row within 16-row tile
  const int lcol_off = (lane >> 4) << 4;                    // +16B for k8-15 subs

  prefetch(0, 0);

  for (int ch = 0; ch < nch; ++ch) {
    if (ch + 1 < nch) prefetch(ch + 1, (ch + 1) & 1);
    if (ch + 1 < nch) { CP_WAIT(1); } else { CP_WAIT(0); }
    __syncthreads();

    const uint32_t stb = sb + (ch & 1) * STAGE_BYTES;
#pragma unroll
    for (int ks = 0; ks < 4; ++ks) {
      uint32_t ah[2][4], al[2][4], bh[8][2], bl[8][2];
#pragma unroll
      for (int mt = 0; mt < 2; ++mt) {
        int lrow = warp_m * 32 + mt * 16 + lrow_off;
        uint32_t off = SWZ((uint32_t)(lrow * 128 + ks * 32 + lcol_off));
        ldsm_x4(ah[mt], stb + ST_A_H + off);
        ldsm_x4(al[mt], stb + ST_A_L + off);
      }
#pragma unroll
      for (int p = 0; p < 4; ++p) {
        int lrow = warp_n * 64 + p * 16 + lrow_off;
        uint32_t off = SWZ((uint32_t)(lrow * 128 + ks * 32 + lcol_off));
        uint32_t r[4];
        ldsm_x4(r, stb + ST_B_H + off);
        bh[2 * p][0] = r[0]; bh[2 * p][1] = r[2];
        bh[2 * p + 1][0] = r[1]; bh[2 * p + 1][1] = r[3];
        ldsm_x4(r, stb + ST_B_L + off);
        bl[2 * p][0] = r[0]; bl[2 * p][1] = r[2];
        bl[2 * p + 1][0] = r[1]; bl[2 * p + 1][1] = r[3];
      }
#pragma unroll
      for (int mt = 0; mt < 2; ++mt)
#pragma unroll
        for (int nt = 0; nt < 8; ++nt) {
          mma_bf16(acc[mt][nt], ah[mt], bh[nt]);
          mma_bf16(acc[mt][nt], ah[mt], bl[nt]);
          mma_bf16(acc[mt][nt], al[mt], bh[nt]);
        }
    }
    __syncthreads();
  }

  // epilogue: C frag mapping: c0,c1 -> row g, cols 2i,2i+1 ; c2,c3 -> row g+8
  const int g = lane >> 2, i2 = (lane & 3) * 2;
#pragma unroll
  for (int mt = 0; mt < 2; ++mt) {
    int r0 = m0 + warp_m * 32 + mt * 16 + g;
#pragma unroll
    for (int nt = 0; nt < 8; ++nt) {
      int col = n0 + warp_n * 64 + nt * 8 + i2;
      float2* p0 = (float2*)(C + (size_t)r0 * N + col);
      float2* p1 = (float2*)(C + (size_t)(r0 + 8) * N + col);
      *p0 = make_float2(acc[mt][nt][0], acc[mt][nt][1]);
      *p1 = make_float2(acc[mt][nt][2], acc[mt][nt][3]);
    }
  }
}

// =====================================================================
// RoPE — sign-flipped halves (validated): pairs (j, j+64), NEGATIVE angle.
// =====================================================================
__global__ void rope_kernel() {
  int idx = blockIdx.x * blockDim.x + threadIdx.x;
  const int total = S_LEN * (NH + NKV) * 64;
  if (idx >= total) return;
  int j = idx & 63;
  int rest = idx >> 6;
  int head = rest % (NH + NKV);
  int s = rest / (NH + NKV);

  float inv_freq = (float)pow(10000.0, -(double)j / 64.0);
  float ang = (float)s * inv_freq;
  float c, sn;
  sincosf(ang, &c, &sn);

  float* base;
  if (head < NH)
    base = g_q + (size_t)s * QDIM + head * HD;
  else
    base = g_k + (size_t)s * KVDIM + (head - NH) * HD;
  float x1 = base[j], x2 = base[j + 64];
  base[j] = x1 * c + x2 * sn;
  base[j + 64] = x2 * c - x1 * sn;
}

// =====================================================================
// Block-sparse attention (validated R15 version, unchanged).
// =====================================================================
#define ATTN_SMEM_FLOATS (3 * 128 * PAD + 128)
#define ATTN_SMEM_BYTES (ATTN_SMEM_FLOATS * 4)

__global__ __launch_bounds__(256, 1) void attn_kernel() {
  extern __shared__ float sm[];
  float* Qt = sm;
  float* KVt = sm + 128 * PAD;
  float* St = sm + 2 * 128 * PAD;
  float* s_l = sm + 3 * 128 * PAD;

  const int i = blockIdx.x;
  const int h = blockIdx.y;
  const int kvh = h >> 2;
  const int tid = threadIdx.x;
  const int tr = tid >> 4;
  const int tc = tid & 15;
  const float scale = 0.08838834764831845f;

  const float* qg = g_q + (size_t)(i * 128) * QDIM + h * HD;
#pragma unroll
  for (int it = 0; it < 16; ++it) {
    int fid = it * 256 + tid;
    int r = fid >> 5;
    int d0 = (fid & 31) * 4;
    float4 t = *reinterpret_cast<const float4*>(&qg[(size_t)r * QDIM + d0]);
    Qt[(d0 + 0) * PAD + r] = t.x * scale;
    Qt[(d0 + 1) * PAD + r] = t.y * scale;
    Qt[(d0 + 2) * PAD + r] = t.z * scale;
    Qt[(d0 + 3) * PAD + r] = t.w * scale;
  }
  if (tid < 128) s_l[tid] = 0.0f;
  float accO[8][8] = {};
  __syncthreads();

  for (int b = -1; b < 8; ++b) {
    const int kb = (b < 0) ? 0 : (i - 7 + b);
    if (b >= 0 && kb < 1) continue;

    const float* kg = g_k + (size_t)(kb * 128) * KVDIM + kvh * HD;
#pragma unroll
    for (int it = 0; it < 16; ++it) {
      int fid = it * 256 + tid;
      int r = fid >> 5;
      int d0 = (fid & 31) * 4;
      float4 t = *reinterpret_cast<const float4*>(&kg[(size_t)r * KVDIM + d0]);
      KVt[(d0 + 0) * PAD + r] = t.x;
      KVt[(d0 + 1) * PAD + r] = t.y;
      KVt[(d0 + 2) * PAD + r] = t.z;
      KVt[(d0 + 3) * PAD + r] = t.w;
    }
    __syncthreads();

    float accS[8][8] = {};
#pragma unroll 2
    for (int d = 0; d < 128; ++d) {
      float regK[8], regQ[8];
      *reinterpret_cast<float4*>(&regK[0]) =
          *reinterpret_cast<const float4*>(&KVt[d * PAD + tr * 8]);
      *reinterpret_cast<float4*>(&regK[4]) =
          *reinterpret_cast<const float4*>(&KVt[d * PAD + tr * 8 + 4]);
      *reinterpret_cast<float4*>(&regQ[0]) =
          *reinterpret_cast<const float4*>(&Qt[d * PAD + tc * 8]);
      *reinterpret_cast<float4*>(&regQ[4]) =
          *reinterpret_cast<const float4*>(&Qt[d * PAD + tc * 8 + 4]);
#pragma unroll
      for (int a = 0; a < 8; ++a)
#pragma unroll
        for (int c = 0; c < 8; ++c) accS[a][c] += regK[a] * regQ[c];
    }

#pragma unroll
    for (int a = 0; a < 8; ++a) {
      const int kpos = kb * 128 + tr * 8 + a;
      float p[8];
#pragma unroll
      for (int c = 0; c < 8; ++c) {
        const int qpos = i * 128 + tc * 8 + c;
        p[c] = (kpos > qpos) ? 0.0f : expf(accS[a][c]);
      }
      float4 o0, o1;
      o0.x = p[0]; o0.y = p[1]; o0.z = p[2]; o0.w = p[3];
      o1.x = p[4]; o1.y = p[5]; o1.z = p[6]; o1.w = p[7];
      *reinterpret_cast<float4*>(&St[(tr * 8 + a) * PAD + tc * 8]) = o0;
      *reinterpret_cast<float4*>(&St[(tr * 8 + a) * PAD + tc * 8 + 4]) = o1;
    }
    __syncthreads();

    const float* vg = g_v + (size_t)(kb * 128) * KVDIM + kvh * HD;
#pragma unroll
    for (int it = 0; it < 16; ++it) {
      int fid = it * 256 + tid;
      int r = fid >> 5;
      int d0 = (fid & 31) * 4;
      *reinterpret_cast<float4*>(&KVt[r * PAD + d0]) =
          *reinterpret_cast<const float4*>(&vg[(size_t)r * KVDIM + d0]);
    }

    if (tid < 128) {
      const int q = tid;
      float sum = 0.0f;
      for (int k = 0; k < 128; ++k) sum += St[k * PAD + q];
      s_l[q] += sum;
    }
    __syncthreads();

#pragma unroll 2
    for (int k = 0; k < 128; ++k) {
      float regP[8], regV[8];
      *reinterpret_cast<float4*>(&regP[0]) =
          *reinterpret_cast<const float4*>(&St[k * PAD + tr * 8]);
      *reinterpret_cast<float4*>(&regP[4]) =
          *reinterpret_cast<const float4*>(&St[k * PAD + tr * 8 + 4]);
      *reinterpret_cast<float4*>(&regV[0]) =
          *reinterpret_cast<const float4*>(&KVt[k * PAD + tc * 8]);
      *reinterpret_cast<float4*>(&regV[4]) =
          *reinterpret_cast<const float4*>(&KVt[k * PAD + tc * 8 + 4]);
#pragma unroll
      for (int a = 0; a < 8; ++a)
#pragma unroll
        for (int c = 0; c < 8; ++c) accO[a][c] += regP[a] * regV[c];
    }
    __syncthreads();
  }

  float* og = g_att + (size_t)(i * 128) * QDIM + h * HD;
#pragma unroll
  for (int a = 0; a < 8; ++a) {
    float inv = 1.0f / s_l[tr * 8 + a];
    float4 o0, o1;
    o0.x = accO[a][0] * inv; o0.y = accO[a][1] * inv;
    o0.z = accO[a][2] * inv; o0.w = accO[a][3] * inv;
    o1.x = accO[a][4] * inv; o1.y = accO[a][5] * inv;
    o1.z = accO[a][6] * inv; o1.w = accO[a][7] * inv;
    *reinterpret_cast<float4*>(&og[(size_t)(tr * 8 + a) * QDIM + tc * 8]) = o0;
    *reinterpret_cast<float4*>(&og[(size_t)(tr * 8 + a) * QDIM + tc * 8 + 4]) = o1;
  }
}

// =====================================================================
// Launch orchestration
// =====================================================================
extern "C" void kernel_launch(void* const* d_in, const int* in_sizes, int n_in,
                              void* d_out, int out_size) {
  (void)in_sizes; (void)n_in; (void)out_size;
  const float* hs = (const float*)d_in[0];
  const float* wq = (const float*)d_in[1];
  const float* wk = (const float*)d_in[2];
  const float* wv = (const float*)d_in[3];
  const float* wo = (const float*)d_in[4];
  float* out = (float*)d_out;

  float *qp, *kp, *vp, *ap;
  __nv_bfloat16 *ah, *al, *bh, *bl;
  cudaGetSymbolAddress((void**)&qp, g_q);
  cudaGetSymbolAddress((void**)&kp, g_k);
  cudaGetSymbolAddress((void**)&vp, g_v);
  cudaGetSymbolAddress((void**)&ap, g_att);
  cudaGetSymbolAddress((void**)&ah, g_ah);
  cudaGetSymbolAddress((void**)&al, g_al);
  cudaGetSymbolAddress((void**)&bh, g_bh);
  cudaGetSymbolAddress((void**)&bl, g_bl);

  cudaFuncSetAttribute(attn_kernel, cudaFuncAttributeMaxDynamicSharedMemorySize,
                       ATTN_SMEM_BYTES);
  cudaFuncSetAttribute(mma_gemm, cudaFuncAttributeMaxDynamicSharedMemorySize, MMA_SMEM);

  const long nA = (long)S_LEN * HIDDEN;
  dim3 t32x8(32, 8);

  // split hidden_states
  split_rows<<<(unsigned)((nA + 255) / 256), 256>>>(hs, ah, al, nA);

  // q projection
  transpose_split<<<dim3(QDIM / 32, HIDDEN / 32), t32x8>>>(wq, bh, bl, HIDDEN, QDIM);
  mma_gemm<<<dim3(QDIM / 128, S_LEN / 128), 256, MMA_SMEM>>>(
      S_LEN, QDIM, HIDDEN, ah, al, bh, bl, qp);

  // k projection
  transpose_split<<<dim3(KVDIM / 32, HIDDEN / 32), t32x8>>>(wk, bh, bl, HIDDEN, KVDIM);
  mma_gemm<<<dim3(KVDIM / 128, S_LEN / 128), 256, MMA_SMEM>>>(
      S_LEN, KVDIM, HIDDEN, ah, al, bh, bl, kp);

  // v projection
  transpose_split<<<dim3(KVDIM / 32, HIDDEN / 32), t32x8>>>(wv, bh, bl, HIDDEN, KVDIM);
  mma_gemm<<<dim3(KVDIM / 128, S_LEN / 128), 256, MMA_SMEM>>>(
      S_LEN, KVDIM, HIDDEN, ah, al, bh, bl, vp);

  // rope (sign-flipped convention)
  {
    int total = S_LEN * (NH + NKV) * 64;
    rope_kernel<<<(total + 255) / 256, 256>>>();
  }

  // attention
  attn_kernel<<<dim3(NB, NH), 256, ATTN_SMEM_BYTES>>>();

  // output projection
  split_rows<<<(unsigned)((nA + 255) / 256), 256>>>(ap, ah, al, nA);
  transpose_split<<<dim3(HIDDEN / 32, QDIM / 32), t32x8>>>(wo, bh, bl, QDIM, HIDDEN);
  mma_gemm<<<dim3(HIDDEN / 128, S_LEN / 128), 256, MMA_SMEM>>>(
      S_LEN, HIDDEN, QDIM, ah, al, bh, bl, out);
}